// round 1
// baseline (speedup 1.0000x reference)
#include <cuda_runtime.h>
#include <math.h>

#define B_ 4
#define T_ 1024
#define D_ 1024
#define H_ 16
#define DH_ 64
#define E_ 8
#define FF_ 4096
#define BT_ (B_*T_)
#define TOPK_ 2
#define NASSIGN (BT_*TOPK_)

// ---------------- scratch (device globals; no allocation allowed) ----------
__device__ float g_h[BT_ * D_];                 // ln1(x)+c, 16 MB
__device__ float g_qkv[BT_ * 3 * D_];           // 48 MB
__device__ float g_o[BT_ * D_];                 // attention out, 16 MB
__device__ float g_x1[BT_ * D_];                // x + proj(o), 16 MB
__device__ float g_hid[(size_t)NASSIGN * FF_];  // 128 MB
__device__ float g_contrib[NASSIGN * D_];       // 32 MB
__device__ int   g_count[E_];
__device__ int   g_assign[E_ * BT_];
__device__ float g_wt[NASSIGN];

__device__ __forceinline__ float gelu_exact(float x) {
    return 0.5f * x * (1.0f + erff(x * 0.70710678118654752440f));
}

// ---------------- init ----------------
__global__ void zero_counts_kernel(int* cnt) {
    if (threadIdx.x < E_) cnt[threadIdx.x] = 0;
}

// ---------------- LayerNorm (+ optional additive cond) --------------------
// one block per token, 256 threads, D=1024
__global__ void __launch_bounds__(256) ln_kernel(
    const float* __restrict__ x, const float* __restrict__ w,
    const float* __restrict__ c, float* __restrict__ out)
{
    int t = blockIdx.x;
    int b = t / T_;
    int tid = threadIdx.x;
    const float* xr = x + (size_t)t * D_;
    float lv[4];
    float s = 0.f, ss = 0.f;
#pragma unroll
    for (int i = 0; i < 4; ++i) {
        lv[i] = xr[tid + i * 256];
        s += lv[i];
        ss += lv[i] * lv[i];
    }
    __shared__ float red0[8], red1[8];
#pragma unroll
    for (int o = 16; o; o >>= 1) {
        s  += __shfl_xor_sync(0xffffffffu, s, o);
        ss += __shfl_xor_sync(0xffffffffu, ss, o);
    }
    if ((tid & 31) == 0) { red0[tid >> 5] = s; red1[tid >> 5] = ss; }
    __syncthreads();
    if (tid < 32) {
        s  = (tid < 8) ? red0[tid] : 0.f;
        ss = (tid < 8) ? red1[tid] : 0.f;
#pragma unroll
        for (int o = 4; o; o >>= 1) {
            s  += __shfl_xor_sync(0xffffffffu, s, o);
            ss += __shfl_xor_sync(0xffffffffu, ss, o);
        }
        if (tid == 0) { red0[0] = s; red1[0] = ss; }
    }
    __syncthreads();
    float mu  = red0[0] * (1.0f / D_);
    float var = red1[0] * (1.0f / D_) - mu * mu;
    float inv = rsqrtf(var + 1e-5f);
#pragma unroll
    for (int i = 0; i < 4; ++i) {
        int d = tid + i * 256;
        float v = (lv[i] - mu) * inv * w[d];
        if (c) v += c[(size_t)b * D_ + d];
        out[(size_t)t * D_ + d] = v;
    }
}

// ---------------- dense SGEMM: C[M,N] = A[M,K] * B[N,K]^T (+ residual) -----
// BM=BN=128, BK=16, 256 threads, 8x8 per thread. M,N multiples of 128.
template<bool RESID>
__global__ void __launch_bounds__(256) sgemm_nt(
    const float* __restrict__ A, const float* __restrict__ Bm,
    float* __restrict__ C, const float* __restrict__ R,
    int M, int N, int K)
{
    __shared__ float As[16][132];
    __shared__ float Bs[16][132];
    int tid = threadIdx.x;
    int m0 = blockIdx.y * 128, n0 = blockIdx.x * 128;
    int ra = tid >> 2;            // 0..63
    int ca = (tid & 3) << 2;      // 0,4,8,12
    int tx = tid & 15, ty = tid >> 4;

    float acc[8][8];
#pragma unroll
    for (int i = 0; i < 8; ++i)
#pragma unroll
        for (int j = 0; j < 8; ++j) acc[i][j] = 0.f;

    const float* Ap = A + (size_t)(m0 + ra) * K + ca;
    const float* Bp = Bm + (size_t)(n0 + ra) * K + ca;

    for (int k0 = 0; k0 < K; k0 += 16) {
#pragma unroll
        for (int p = 0; p < 2; ++p) {
            float4 va = *(const float4*)(Ap + (size_t)p * 64 * K + k0);
            As[ca + 0][ra + p * 64] = va.x;
            As[ca + 1][ra + p * 64] = va.y;
            As[ca + 2][ra + p * 64] = va.z;
            As[ca + 3][ra + p * 64] = va.w;
            float4 vb = *(const float4*)(Bp + (size_t)p * 64 * K + k0);
            Bs[ca + 0][ra + p * 64] = vb.x;
            Bs[ca + 1][ra + p * 64] = vb.y;
            Bs[ca + 2][ra + p * 64] = vb.z;
            Bs[ca + 3][ra + p * 64] = vb.w;
        }
        __syncthreads();
#pragma unroll
        for (int k = 0; k < 16; ++k) {
            float a[8], b[8];
            *(float4*)(&a[0]) = *(const float4*)(&As[k][ty * 8]);
            *(float4*)(&a[4]) = *(const float4*)(&As[k][ty * 8 + 4]);
            *(float4*)(&b[0]) = *(const float4*)(&Bs[k][tx * 8]);
            *(float4*)(&b[4]) = *(const float4*)(&Bs[k][tx * 8 + 4]);
#pragma unroll
            for (int i = 0; i < 8; ++i)
#pragma unroll
                for (int j = 0; j < 8; ++j) acc[i][j] += a[i] * b[j];
        }
        __syncthreads();
    }

#pragma unroll
    for (int i = 0; i < 8; ++i) {
        int m = m0 + ty * 8 + i;
        float* Cp = C + (size_t)m * N + n0 + tx * 8;
#pragma unroll
        for (int j = 0; j < 8; j += 4) {
            float4 v;
            v.x = acc[i][j + 0]; v.y = acc[i][j + 1];
            v.z = acc[i][j + 2]; v.w = acc[i][j + 3];
            if (RESID) {
                const float4 r4 = *(const float4*)(R + (size_t)m * N + n0 + tx * 8 + j);
                v.x += r4.x; v.y += r4.y; v.z += r4.z; v.w += r4.w;
            }
            *(float4*)(Cp + j) = v;
        }
    }
}

// ---------------- flash attention (fp32, causal) ---------------------------
// grid: (T/64, B*H). 64-row q tiles, 32-key tiles.
__global__ void __launch_bounds__(256) attn_kernel(
    const float* __restrict__ qkv, float* __restrict__ O)
{
    __shared__ float Qs[64][68];
    __shared__ float Ks[32][68];
    __shared__ float Vs[32][68];
    __shared__ float Ps[64][36];

    int bh = blockIdx.y;
    int b = bh >> 4, h = bh & 15;
    int q0 = blockIdx.x * 64;
    int tid = threadIdx.x;
    int tx = tid & 15, ty = tid >> 4;
    int lr = tid >> 4;             // 0..15 (row in load pass)
    int lc = (tid & 15) << 2;      // 0..60

    const float* qbase = qkv + (size_t)(b * T_) * 3 * D_ + h * DH_;
    const float* kbase = qbase + D_;
    const float* vbase = qbase + 2 * D_;

#pragma unroll
    for (int p = 0; p < 4; ++p) {
        int r = lr + p * 16;
        *(float4*)&Qs[r][lc] = *(const float4*)(qbase + (size_t)(q0 + r) * 3 * D_ + lc);
    }

    float Oacc[4][4];
    float m_i[4], l_i[4];
#pragma unroll
    for (int r = 0; r < 4; ++r) {
        m_i[r] = -1e30f; l_i[r] = 0.f;
#pragma unroll
        for (int d = 0; d < 4; ++d) Oacc[r][d] = 0.f;
    }
    __syncthreads();

    int nkt = (q0 + 64) / 32;
    for (int kt = 0; kt < nkt; ++kt) {
        int k0 = kt * 32;
#pragma unroll
        for (int p = 0; p < 2; ++p) {
            int r = lr + p * 16;
            *(float4*)&Ks[r][lc] = *(const float4*)(kbase + (size_t)(k0 + r) * 3 * D_ + lc);
            *(float4*)&Vs[r][lc] = *(const float4*)(vbase + (size_t)(k0 + r) * 3 * D_ + lc);
        }
        __syncthreads();

        // S = Q K^T : thread owns rows ty*4..+3, cols tx*2..+1
        float s[4][2];
#pragma unroll
        for (int r = 0; r < 4; ++r) { s[r][0] = 0.f; s[r][1] = 0.f; }
#pragma unroll
        for (int d = 0; d < 64; d += 4) {
            float4 kv0 = *(const float4*)&Ks[tx * 2 + 0][d];
            float4 kv1 = *(const float4*)&Ks[tx * 2 + 1][d];
#pragma unroll
            for (int r = 0; r < 4; ++r) {
                float4 qv = *(const float4*)&Qs[ty * 4 + r][d];
                s[r][0] += qv.x * kv0.x + qv.y * kv0.y + qv.z * kv0.z + qv.w * kv0.w;
                s[r][1] += qv.x * kv1.x + qv.y * kv1.y + qv.z * kv1.z + qv.w * kv1.w;
            }
        }
        // scale + causal mask
#pragma unroll
        for (int r = 0; r < 4; ++r) {
            int qg = q0 + ty * 4 + r;
#pragma unroll
            for (int c2 = 0; c2 < 2; ++c2) {
                int kg = k0 + tx * 2 + c2;
                s[r][c2] = (kg <= qg) ? s[r][c2] * 0.125f : -1e30f;
            }
        }
        // online softmax (row groups = 16 lanes sharing ty)
#pragma unroll
        for (int r = 0; r < 4; ++r) {
            float v = fmaxf(s[r][0], s[r][1]);
#pragma unroll
            for (int o = 8; o; o >>= 1) v = fmaxf(v, __shfl_xor_sync(0xffffffffu, v, o, 16));
            float mnew = fmaxf(m_i[r], v);
            float p0 = expf(s[r][0] - mnew);
            float p1 = expf(s[r][1] - mnew);
            s[r][0] = p0; s[r][1] = p1;
            float rs = p0 + p1;
#pragma unroll
            for (int o = 8; o; o >>= 1) rs += __shfl_xor_sync(0xffffffffu, rs, o, 16);
            float alpha = expf(m_i[r] - mnew);
            l_i[r] = l_i[r] * alpha + rs;
            m_i[r] = mnew;
#pragma unroll
            for (int d = 0; d < 4; ++d) Oacc[r][d] *= alpha;
        }
        // write P
#pragma unroll
        for (int r = 0; r < 4; ++r) {
            Ps[ty * 4 + r][tx * 2 + 0] = s[r][0];
            Ps[ty * 4 + r][tx * 2 + 1] = s[r][1];
        }
        __syncthreads();
        // O += P V : dcols tx*4..+3
#pragma unroll
        for (int kk = 0; kk < 32; kk += 4) {
            float4 vv0 = *(const float4*)&Vs[kk + 0][tx * 4];
            float4 vv1 = *(const float4*)&Vs[kk + 1][tx * 4];
            float4 vv2 = *(const float4*)&Vs[kk + 2][tx * 4];
            float4 vv3 = *(const float4*)&Vs[kk + 3][tx * 4];
#pragma unroll
            for (int r = 0; r < 4; ++r) {
                float4 pv = *(const float4*)&Ps[ty * 4 + r][kk];
                Oacc[r][0] += pv.x * vv0.x + pv.y * vv1.x + pv.z * vv2.x + pv.w * vv3.x;
                Oacc[r][1] += pv.x * vv0.y + pv.y * vv1.y + pv.z * vv2.y + pv.w * vv3.y;
                Oacc[r][2] += pv.x * vv0.z + pv.y * vv1.z + pv.z * vv2.z + pv.w * vv3.z;
                Oacc[r][3] += pv.x * vv0.w + pv.y * vv1.w + pv.z * vv2.w + pv.w * vv3.w;
            }
        }
        __syncthreads();
    }

#pragma unroll
    for (int r = 0; r < 4; ++r) {
        float invl = 1.0f / l_i[r];
        int qg = q0 + ty * 4 + r;
        float4 v;
        v.x = Oacc[r][0] * invl; v.y = Oacc[r][1] * invl;
        v.z = Oacc[r][2] * invl; v.w = Oacc[r][3] * invl;
        *(float4*)(O + (size_t)(b * T_ + qg) * D_ + h * DH_ + tx * 4) = v;
    }
}

// ---------------- router: softmax + clip + top-2 + normalize ---------------
__global__ void __launch_bounds__(256) router_kernel(
    const float* __restrict__ X, const float* __restrict__ RW,
    int* __restrict__ cnt, int* __restrict__ assign, float* __restrict__ wt)
{
    int t = blockIdx.x;
    int tid = threadIdx.x;
    int w = tid >> 5, lane = tid & 31;
    const float* xr = X + (size_t)t * D_;
    const float* rw = RW + (size_t)w * D_;
    float s = 0.f;
    for (int d = lane; d < D_; d += 32) s += xr[d] * rw[d];
#pragma unroll
    for (int o = 16; o; o >>= 1) s += __shfl_xor_sync(0xffffffffu, s, o);
    __shared__ float lg[E_];
    if (lane == 0) lg[w] = s;
    __syncthreads();
    if (tid == 0) {
        float mx = -1e30f;
#pragma unroll
        for (int e = 0; e < E_; ++e) mx = fmaxf(mx, lg[e]);
        float p[E_], sum = 0.f;
#pragma unroll
        for (int e = 0; e < E_; ++e) { p[e] = expf(lg[e] - mx); sum += p[e]; }
        float invs = 1.0f / sum;
#pragma unroll
        for (int e = 0; e < E_; ++e) {
            float pe = p[e] * invs;
            pe = fminf(fmaxf(pe + 1e-9f, 1e-9f), 1.0f - 1e-9f);
            p[e] = pe;
        }
        int e0 = 0;
#pragma unroll
        for (int e = 1; e < E_; ++e) if (p[e] > p[e0]) e0 = e;
        int e1 = -1;
#pragma unroll
        for (int e = 0; e < E_; ++e) {
            if (e == e0) continue;
            if (e1 < 0 || p[e] > p[e1]) e1 = e;
        }
        float inv = 1.0f / (p[e0] + p[e1]);
        int pos0 = atomicAdd(&cnt[e0], 1);
        assign[e0 * BT_ + pos0] = 2 * t;
        int pos1 = atomicAdd(&cnt[e1], 1);
        assign[e1 * BT_ + pos1] = 2 * t + 1;
        wt[2 * t]     = p[e0] * inv;
        wt[2 * t + 1] = p[e1] * inv;
    }
}

// ---------------- grouped MoE GEMM1: hid = gelu(X W1^T), gathered rows -----
__global__ void __launch_bounds__(256) moe_gemm1(
    const float* __restrict__ X, const float* __restrict__ W1,
    float* __restrict__ Hid, const int* __restrict__ cnt,
    const int* __restrict__ assign)
{
    int e = blockIdx.z;
    int n_e = cnt[e];
    int m0 = blockIdx.y * 128;
    if (m0 >= n_e) return;
    int n0 = blockIdx.x * 128;

    __shared__ float As[16][132];
    __shared__ float Bs[16][132];
    int tid = threadIdx.x;
    int ra = tid >> 2, ca = (tid & 3) << 2;
    int tx = tid & 15, ty = tid >> 4;
    const float* Bm = W1 + (size_t)e * FF_ * D_;
    const int* lst = assign + e * BT_;

    int tok[2]; bool vrow[2];
#pragma unroll
    for (int p = 0; p < 2; ++p) {
        int rg = m0 + ra + p * 64;
        vrow[p] = (rg < n_e);
        tok[p] = vrow[p] ? (lst[rg] >> 1) : 0;
    }

    float acc[8][8];
#pragma unroll
    for (int i = 0; i < 8; ++i)
#pragma unroll
        for (int j = 0; j < 8; ++j) acc[i][j] = 0.f;

    const float* Bp = Bm + (size_t)(n0 + ra) * D_ + ca;

    for (int k0 = 0; k0 < D_; k0 += 16) {
#pragma unroll
        for (int p = 0; p < 2; ++p) {
            float4 va = make_float4(0.f, 0.f, 0.f, 0.f);
            if (vrow[p]) va = *(const float4*)(X + (size_t)tok[p] * D_ + k0 + ca);
            As[ca + 0][ra + p * 64] = va.x;
            As[ca + 1][ra + p * 64] = va.y;
            As[ca + 2][ra + p * 64] = va.z;
            As[ca + 3][ra + p * 64] = va.w;
            float4 vb = *(const float4*)(Bp + (size_t)p * 64 * D_ + k0);
            Bs[ca + 0][ra + p * 64] = vb.x;
            Bs[ca + 1][ra + p * 64] = vb.y;
            Bs[ca + 2][ra + p * 64] = vb.z;
            Bs[ca + 3][ra + p * 64] = vb.w;
        }
        __syncthreads();
#pragma unroll
        for (int k = 0; k < 16; ++k) {
            float a[8], b[8];
            *(float4*)(&a[0]) = *(const float4*)(&As[k][ty * 8]);
            *(float4*)(&a[4]) = *(const float4*)(&As[k][ty * 8 + 4]);
            *(float4*)(&b[0]) = *(const float4*)(&Bs[k][tx * 8]);
            *(float4*)(&b[4]) = *(const float4*)(&Bs[k][tx * 8 + 4]);
#pragma unroll
            for (int i = 0; i < 8; ++i)
#pragma unroll
                for (int j = 0; j < 8; ++j) acc[i][j] += a[i] * b[j];
        }
        __syncthreads();
    }

#pragma unroll
    for (int i = 0; i < 8; ++i) {
        int mg = m0 + ty * 8 + i;
        if (mg >= n_e) continue;
        int a = lst[mg];
        float* Hp = Hid + (size_t)a * FF_ + n0 + tx * 8;
#pragma unroll
        for (int j = 0; j < 8; j += 4) {
            float4 v;
            v.x = gelu_exact(acc[i][j + 0]);
            v.y = gelu_exact(acc[i][j + 1]);
            v.z = gelu_exact(acc[i][j + 2]);
            v.w = gelu_exact(acc[i][j + 3]);
            *(float4*)(Hp + j) = v;
        }
    }
}

// ---------------- grouped MoE GEMM2: contrib = wt * (hid W2^T) -------------
__global__ void __launch_bounds__(256) moe_gemm2(
    const float* __restrict__ Hid, const float* __restrict__ W2,
    float* __restrict__ Con, const int* __restrict__ cnt,
    const int* __restrict__ assign, const float* __restrict__ wt)
{
    int e = blockIdx.z;
    int n_e = cnt[e];
    int m0 = blockIdx.y * 128;
    if (m0 >= n_e) return;
    int n0 = blockIdx.x * 128;

    __shared__ float As[16][132];
    __shared__ float Bs[16][132];
    int tid = threadIdx.x;
    int ra = tid >> 2, ca = (tid & 3) << 2;
    int tx = tid & 15, ty = tid >> 4;
    const float* Bm = W2 + (size_t)e * D_ * FF_;
    const int* lst = assign + e * BT_;

    int arow[2]; bool vrow[2];
#pragma unroll
    for (int p = 0; p < 2; ++p) {
        int rg = m0 + ra + p * 64;
        vrow[p] = (rg < n_e);
        arow[p] = vrow[p] ? lst[rg] : 0;
    }

    float acc[8][8];
#pragma unroll
    for (int i = 0; i < 8; ++i)
#pragma unroll
        for (int j = 0; j < 8; ++j) acc[i][j] = 0.f;

    const float* Bp = Bm + (size_t)(n0 + ra) * FF_ + ca;

    for (int k0 = 0; k0 < FF_; k0 += 16) {
#pragma unroll
        for (int p = 0; p < 2; ++p) {
            float4 va = make_float4(0.f, 0.f, 0.f, 0.f);
            if (vrow[p]) va = *(const float4*)(Hid + (size_t)arow[p] * FF_ + k0 + ca);
            As[ca + 0][ra + p * 64] = va.x;
            As[ca + 1][ra + p * 64] = va.y;
            As[ca + 2][ra + p * 64] = va.z;
            As[ca + 3][ra + p * 64] = va.w;
            float4 vb = *(const float4*)(Bp + (size_t)p * 64 * FF_ + k0);
            Bs[ca + 0][ra + p * 64] = vb.x;
            Bs[ca + 1][ra + p * 64] = vb.y;
            Bs[ca + 2][ra + p * 64] = vb.z;
            Bs[ca + 3][ra + p * 64] = vb.w;
        }
        __syncthreads();
#pragma unroll
        for (int k = 0; k < 16; ++k) {
            float a[8], b[8];
            *(float4*)(&a[0]) = *(const float4*)(&As[k][ty * 8]);
            *(float4*)(&a[4]) = *(const float4*)(&As[k][ty * 8 + 4]);
            *(float4*)(&b[0]) = *(const float4*)(&Bs[k][tx * 8]);
            *(float4*)(&b[4]) = *(const float4*)(&Bs[k][tx * 8 + 4]);
#pragma unroll
            for (int i = 0; i < 8; ++i)
#pragma unroll
                for (int j = 0; j < 8; ++j) acc[i][j] += a[i] * b[j];
        }
        __syncthreads();
    }

#pragma unroll
    for (int i = 0; i < 8; ++i) {
        int mg = m0 + ty * 8 + i;
        if (mg >= n_e) continue;
        int a = lst[mg];
        float wv = wt[a];
        float* Cp = Con + (size_t)a * D_ + n0 + tx * 8;
#pragma unroll
        for (int j = 0; j < 8; j += 4) {
            float4 v;
            v.x = wv * acc[i][j + 0];
            v.y = wv * acc[i][j + 1];
            v.z = wv * acc[i][j + 2];
            v.w = wv * acc[i][j + 3];
            *(float4*)(Cp + j) = v;
        }
    }
}

// ---------------- combine: out += contrib[slot0] + contrib[slot1] ----------
__global__ void __launch_bounds__(256) combine_kernel(
    const float* __restrict__ Con, float* __restrict__ out)
{
    int i = blockIdx.x * 256 + threadIdx.x;   // over BT*D
    int t = i >> 10;
    int d = i & 1023;
    out[i] += Con[(size_t)(2 * t) * D_ + d] + Con[(size_t)(2 * t + 1) * D_ + d];
}

// ---------------- launch ----------------
extern "C" void kernel_launch(void* const* d_in, const int* in_sizes, int n_in,
                              void* d_out, int out_size)
{
    const float* x        = (const float*)d_in[0];
    const float* c        = (const float*)d_in[1];
    const float* ln1_w    = (const float*)d_in[2];
    const float* w_qkv    = (const float*)d_in[3];
    const float* w_proj   = (const float*)d_in[4];
    const float* ln2_w    = (const float*)d_in[5];
    const float* router_w = (const float*)d_in[6];
    const float* ew1      = (const float*)d_in[7];
    const float* ew2      = (const float*)d_in[8];
    float* out = (float*)d_out;

    float *ph, *pqkv, *po, *px1, *phid, *pcon, *pwt;
    int *pcnt, *pasn;
    cudaGetSymbolAddress((void**)&ph,   g_h);
    cudaGetSymbolAddress((void**)&pqkv, g_qkv);
    cudaGetSymbolAddress((void**)&po,   g_o);
    cudaGetSymbolAddress((void**)&px1,  g_x1);
    cudaGetSymbolAddress((void**)&phid, g_hid);
    cudaGetSymbolAddress((void**)&pcon, g_contrib);
    cudaGetSymbolAddress((void**)&pwt,  g_wt);
    cudaGetSymbolAddress((void**)&pcnt, g_count);
    cudaGetSymbolAddress((void**)&pasn, g_assign);

    zero_counts_kernel<<<1, 32>>>(pcnt);
    // h = ln1(x) + c
    ln_kernel<<<BT_, 256>>>(x, ln1_w, c, ph);
    // qkv = h @ w_qkv^T
    sgemm_nt<false><<<dim3(3 * D_ / 128, BT_ / 128), 256>>>(ph, w_qkv, pqkv, nullptr, BT_, 3 * D_, D_);
    // o = attention(q,k,v)
    attn_kernel<<<dim3(T_ / 64, B_ * H_), 256>>>(pqkv, po);
    // x1 = x + o @ w_proj^T
    sgemm_nt<true><<<dim3(D_ / 128, BT_ / 128), 256>>>(po, w_proj, px1, x, BT_, D_, D_);
    // out = ln2(x1)  (also MoE input)
    ln_kernel<<<BT_, 256>>>(px1, ln2_w, nullptr, out);
    // routing
    router_kernel<<<BT_, 256>>>(out, router_w, pcnt, pasn, pwt);
    // expert GEMMs (grouped, sparse top-2)
    moe_gemm1<<<dim3(FF_ / 128, BT_ / 128, E_), 256>>>(out, ew1, phid, pcnt, pasn);
    moe_gemm2<<<dim3(D_ / 128, BT_ / 128, E_), 256>>>(phid, ew2, pcon, pcnt, pasn, pwt);
    // out += expert contributions
    combine_kernel<<<(BT_ * D_) / 256, 256>>>(pcon, out);
}